// round 2
// baseline (speedup 1.0000x reference)
#include <cuda_runtime.h>
#include <cstdint>

#define BS 128
#define NC 1024
#define U  512
#define F  512
#define FOURU 2048

// ---------------- scratch (no allocations allowed) ----------------
__device__ float g_h0[BS * U];
__device__ float g_c0[BS * U];
__device__ int   g_idx[BS];
__device__ float g_zpart[2][BS * FOURU];   // z = zpart[0] + zpart[1] + bias

// ---------------- helpers ----------------
__device__ __forceinline__ unsigned long long dup2(float v) {
    unsigned long long r;
    asm("mov.b64 %0, {%1, %1};" : "=l"(r) : "f"(v));
    return r;
}

__device__ __forceinline__ void fma2(unsigned long long& d,
                                     unsigned long long a,
                                     unsigned long long b) {
    asm("fma.rn.f32x2 %0, %1, %2, %3;" : "=l"(d) : "l"(a), "l"(b), "l"(d));
}

__device__ __forceinline__ void atomicMaxFloat(float* addr, float val) {
    int* ia = (int*)addr;
    int old = *ia;
    while (__int_as_float(old) < val) {
        int assumed = old;
        old = atomicCAS(ia, assumed, __float_as_int(val));
        if (old == assumed) break;
    }
}

// ---------------- K1: per-row argmax of logits + gather states ----------------
__global__ void k_argmax_gather(const float* __restrict__ logits,
                                const float* __restrict__ h_states,
                                const float* __restrict__ c_states) {
    const int b = blockIdx.x;
    const int t = threadIdx.x;                 // 256 threads
    const float* row = logits + b * NC;

    float best = -3.4e38f;
    int   bi   = 0x7fffffff;
#pragma unroll
    for (int j = 0; j < NC; j += 256) {
        float v = row[j + t];
        int   i = j + t;
        if (v > best || (v == best && i < bi)) { best = v; bi = i; }
    }
#pragma unroll
    for (int off = 16; off; off >>= 1) {
        float ov = __shfl_down_sync(0xffffffffu, best, off);
        int   oi = __shfl_down_sync(0xffffffffu, bi,   off);
        if (ov > best || (ov == best && oi < bi)) { best = ov; bi = oi; }
    }
    __shared__ float sv[8];
    __shared__ int   si[8];
    __shared__ int   s_idx;
    if ((t & 31) == 0) { sv[t >> 5] = best; si[t >> 5] = bi; }
    __syncthreads();
    if (t == 0) {
        best = sv[0]; bi = si[0];
#pragma unroll
        for (int w = 1; w < 8; ++w)
            if (sv[w] > best || (sv[w] == best && si[w] < bi)) { best = sv[w]; bi = si[w]; }
        s_idx = bi;
        g_idx[b] = bi;
    }
    __syncthreads();
    const int idx = s_idx;

    const float4* hs = (const float4*)(h_states + idx * U);
    const float4* cs = (const float4*)(c_states + idx * U);
    float4* hd = (float4*)(g_h0 + b * U);
    float4* cd = (float4*)(g_c0 + b * U);
    if (t < U / 4) { hd[t] = hs[t]; cd[t] = cs[t]; }
}

// ---------------- K2: copy states into output (base for scatter-max) ----------------
__global__ void k_copy_states(const float* __restrict__ h_states,
                              const float* __restrict__ c_states,
                              float* __restrict__ out_newh,
                              float* __restrict__ out_newc) {
    int i = blockIdx.x * blockDim.x + threadIdx.x;   // over NC*U/4 float4s
    if (i < NC * U / 4) {
        ((float4*)out_newh)[i] = ((const float4*)h_states)[i];
        ((float4*)out_newc)[i] = ((const float4*)c_states)[i];
    }
}

// ---------------- K3: fused GEMM  zpart[z] = A_z @ B_z ----------------
// A_0 = x (128x512), B_0 = kernel (512x2048); A_1 = g_h0, B_1 = rec_kernel.
// Tile: 64(M) x 64(N), K-tile 16, 256 threads, 4x4 outputs/thread via f32x2.
#define TM 64
#define TN 64
#define TK 16

__global__ __launch_bounds__(256) void k_gemm(const float* __restrict__ x,
                                              const float* __restrict__ kernelW,
                                              const float* __restrict__ recW) {
    const int half = blockIdx.z;
    const float* __restrict__ A = half ? g_h0 : x;        // [128, 512]
    const float* __restrict__ B = half ? recW : kernelW;  // [512, 2048]
    float* __restrict__ Zout = g_zpart[half];

    __shared__ unsigned long long As2[TK][TM];   // A values duplicated into f32x2 pairs
    __shared__ float Bs[TK][TN];

    const int t = threadIdx.x;
    const int m_blk = blockIdx.y * TM;
    const int n_blk = blockIdx.x * TN;

    const int tm = (t >> 4) * 4;   // 0..60
    const int tn = (t & 15) * 4;   // 0..60

    unsigned long long acc[4][2];
#pragma unroll
    for (int i = 0; i < 4; ++i)
#pragma unroll
        for (int j = 0; j < 2; ++j) acc[i][j] = 0ull;

    // loader coords
    const int am  = t >> 2;          // 0..63
    const int ak0 = (t & 3) * 4;     // 0,4,8,12
    const int bk  = t >> 4;          // 0..15
    const int bn  = (t & 15) * 4;    // 0..60

    const float* Aptr = A + (m_blk + am) * F + ak0;
    const float* Bptr = B + bk * FOURU + n_blk + bn;

    for (int k0 = 0; k0 < F; k0 += TK) {
        float4 av = *(const float4*)Aptr;
        float4 bv = *(const float4*)Bptr;
        __syncthreads();
        As2[ak0 + 0][am] = dup2(av.x);
        As2[ak0 + 1][am] = dup2(av.y);
        As2[ak0 + 2][am] = dup2(av.z);
        As2[ak0 + 3][am] = dup2(av.w);
        *(float4*)&Bs[bk][bn] = bv;
        __syncthreads();

#pragma unroll
        for (int kk = 0; kk < TK; ++kk) {
            ulonglong2 a01 = *(const ulonglong2*)&As2[kk][tm];
            ulonglong2 a23 = *(const ulonglong2*)&As2[kk][tm + 2];
            ulonglong2 b01 = *(const ulonglong2*)&Bs[kk][tn];   // (n0,n1) (n2,n3)
            fma2(acc[0][0], a01.x, b01.x); fma2(acc[0][1], a01.x, b01.y);
            fma2(acc[1][0], a01.y, b01.x); fma2(acc[1][1], a01.y, b01.y);
            fma2(acc[2][0], a23.x, b01.x); fma2(acc[2][1], a23.x, b01.y);
            fma2(acc[3][0], a23.y, b01.x); fma2(acc[3][1], a23.y, b01.y);
        }
        Aptr += TK;
        Bptr += TK * FOURU;
    }

#pragma unroll
    for (int mi = 0; mi < 4; ++mi) {
        float* zr = Zout + (m_blk + tm + mi) * FOURU + n_blk + tn;
        *(unsigned long long*)(zr)     = acc[mi][0];
        *(unsigned long long*)(zr + 2) = acc[mi][1];
    }
}

// ---------------- K4: gates + LSTM cell + scatter-max ----------------
__global__ void k_gates_scatter(const float* __restrict__ bias,
                                float* __restrict__ out_h,
                                float* __restrict__ out_newh,
                                float* __restrict__ out_newc) {
    const int i = blockIdx.x * blockDim.x + threadIdx.x;  // 0 .. BS*U-1
    const int b = i >> 9;     // / U
    const int u = i & (U - 1);

    const float* za = g_zpart[0] + b * FOURU;
    const float* zb = g_zpart[1] + b * FOURU;

    float zi = za[u]         + zb[u]         + bias[u];
    float zf = za[u + U]     + zb[u + U]     + bias[u + U];
    float zg = za[u + 2 * U] + zb[u + 2 * U] + bias[u + 2 * U];
    float zo = za[u + 3 * U] + zb[u + 3 * U] + bias[u + 3 * U];

    float ig = 1.0f / (1.0f + expf(-zi));
    float fg = 1.0f / (1.0f + expf(-zf));
    float gg = tanhf(zg);
    float og = 1.0f / (1.0f + expf(-zo));

    float c0 = g_c0[i];
    float c  = fg * c0 + ig * gg;
    float h  = og * tanhf(c);

    out_h[i] = h;

    const int cls = g_idx[b];
    atomicMaxFloat(&out_newh[cls * U + u], h);
    atomicMaxFloat(&out_newc[cls * U + u], c);
}

// ---------------- launch ----------------
extern "C" void kernel_launch(void* const* d_in, const int* in_sizes, int n_in,
                              void* d_out, int out_size) {
    const float* x        = (const float*)d_in[0];
    const float* logits   = (const float*)d_in[1];
    const float* h_states = (const float*)d_in[2];
    const float* c_states = (const float*)d_in[3];
    const float* kernelW  = (const float*)d_in[4];
    const float* recW     = (const float*)d_in[5];
    const float* bias     = (const float*)d_in[6];

    float* out      = (float*)d_out;
    float* out_h    = out;                    // (128, 512)
    float* out_newh = out + BS * U;           // (1024, 512)
    float* out_newc = out + BS * U + NC * U;  // (1024, 512)

    k_argmax_gather<<<BS, 256>>>(logits, h_states, c_states);
    k_copy_states<<<(NC * U / 4 + 255) / 256, 256>>>(h_states, c_states, out_newh, out_newc);
    dim3 g(FOURU / TN, BS / TM, 2);           // (32, 2, 2) = 128 blocks
    k_gemm<<<g, 256>>>(x, kernelW, recW);
    k_gates_scatter<<<(BS * U) / 256, 256>>>(bias, out_h, out_newh, out_newc);
}

// round 3
// speedup vs baseline: 1.2319x; 1.2319x over previous
#include <cuda_runtime.h>
#include <cstdint>

#define BS 128
#define NC 1024
#define U  512
#define F  512
#define FOURU 2048

// ---------------- scratch (no allocations allowed) ----------------
__device__ float g_h0[BS * U];
__device__ float g_c0[BS * U];
__device__ int   g_idx[BS];
__device__ float g_zpart[2][BS * FOURU];   // z = zpart[0] + zpart[1] + bias

// ---------------- helpers ----------------
__device__ __forceinline__ unsigned long long dup2(float v) {
    unsigned long long r;
    asm("mov.b64 %0, {%1, %1};" : "=l"(r) : "f"(v));
    return r;
}

__device__ __forceinline__ void fma2(unsigned long long& d,
                                     unsigned long long a,
                                     unsigned long long b) {
    asm("fma.rn.f32x2 %0, %1, %2, %3;" : "=l"(d) : "l"(a), "l"(b), "l"(d));
}

__device__ __forceinline__ void atomicMaxFloat(float* addr, float val) {
    int* ia = (int*)addr;
    int old = *ia;
    while (__int_as_float(old) < val) {
        int assumed = old;
        old = atomicCAS(ia, assumed, __float_as_int(val));
        if (old == assumed) break;
    }
}

// fast sigmoid / tanh from ex2.approx + rcp.approx (abs err ~1e-7)
__device__ __forceinline__ float fsig(float x) {
    float e, r;
    asm("ex2.approx.ftz.f32 %0, %1;" : "=f"(e) : "f"(-x * 1.4426950408889634f));
    asm("rcp.approx.ftz.f32 %0, %1;" : "=f"(r) : "f"(1.0f + e));
    return r;
}
__device__ __forceinline__ float ftanh_fast(float x) {
    return 2.0f * fsig(2.0f * x) - 1.0f;
}

// ---------------- K1: per-row argmax of logits + gather states ----------------
__global__ void k_argmax_gather(const float* __restrict__ logits,
                                const float* __restrict__ h_states,
                                const float* __restrict__ c_states) {
    const int b = blockIdx.x;
    const int t = threadIdx.x;                 // 256 threads
    const float* row = logits + b * NC;

    float best = -3.4e38f;
    int   bi   = 0x7fffffff;
#pragma unroll
    for (int j = 0; j < NC; j += 256) {
        float v = row[j + t];
        int   i = j + t;
        if (v > best || (v == best && i < bi)) { best = v; bi = i; }
    }
#pragma unroll
    for (int off = 16; off; off >>= 1) {
        float ov = __shfl_down_sync(0xffffffffu, best, off);
        int   oi = __shfl_down_sync(0xffffffffu, bi,   off);
        if (ov > best || (ov == best && oi < bi)) { best = ov; bi = oi; }
    }
    __shared__ float sv[8];
    __shared__ int   si[8];
    __shared__ int   s_idx;
    if ((t & 31) == 0) { sv[t >> 5] = best; si[t >> 5] = bi; }
    __syncthreads();
    if (t == 0) {
        best = sv[0]; bi = si[0];
#pragma unroll
        for (int w = 1; w < 8; ++w)
            if (sv[w] > best || (sv[w] == best && si[w] < bi)) { best = sv[w]; bi = si[w]; }
        s_idx = bi;
        g_idx[b] = bi;
    }
    __syncthreads();
    const int idx = s_idx;

    const float4* hs = (const float4*)(h_states + idx * U);
    const float4* cs = (const float4*)(c_states + idx * U);
    float4* hd = (float4*)(g_h0 + b * U);
    float4* cd = (float4*)(g_c0 + b * U);
    if (t < U / 4) { hd[t] = hs[t]; cd[t] = cs[t]; }
}

// ---------------- K2: copy states into output (base for scatter-max) ----------------
__global__ void k_copy_states(const float* __restrict__ h_states,
                              const float* __restrict__ c_states,
                              float* __restrict__ out_newh,
                              float* __restrict__ out_newc) {
    int i = blockIdx.x * blockDim.x + threadIdx.x;   // over NC*U/4 float4s
    if (i < NC * U / 4) {
        ((float4*)out_newh)[i] = ((const float4*)h_states)[i];
        ((float4*)out_newc)[i] = ((const float4*)c_states)[i];
    }
}

// ---------------- K3: fused GEMM  zpart[z] = A_z @ B_z (double-buffered) ----------------
// A_0 = x (128x512), B_0 = kernel (512x2048); A_1 = g_h0, B_1 = rec_kernel.
// Tile: 64(M) x 64(N), K-tile 16, 256 threads, 4x4 outputs/thread via f32x2.
#define TM 64
#define TN 64
#define TK 16
#define NIT (F / TK)

__global__ __launch_bounds__(256) void k_gemm(const float* __restrict__ x,
                                              const float* __restrict__ kernelW,
                                              const float* __restrict__ recW) {
    const int half = blockIdx.z;
    const float* __restrict__ A = half ? g_h0 : x;        // [128, 512]
    const float* __restrict__ B = half ? recW : kernelW;  // [512, 2048]
    float* __restrict__ Zout = g_zpart[half];

    // TM+2 pad: keeps 16B alignment for ulonglong2 reads AND de-conflicts the
    // 4 writers sharing `am` (4*528 mod 128 = 64 -> different banks).
    __shared__ unsigned long long As2[2][TK][TM + 2];
    __shared__ float Bs[2][TK][TN];

    const int t = threadIdx.x;
    const int m_blk = blockIdx.y * TM;
    const int n_blk = blockIdx.x * TN;

    const int tm = (t >> 4) * 4;   // 0..60
    const int tn = (t & 15) * 4;   // 0..60

    unsigned long long acc[4][2];
#pragma unroll
    for (int i = 0; i < 4; ++i)
#pragma unroll
        for (int j = 0; j < 2; ++j) acc[i][j] = 0ull;

    // loader coords
    const int am  = t >> 2;          // 0..63
    const int ak0 = (t & 3) * 4;     // 0,4,8,12
    const int bk  = t >> 4;          // 0..15
    const int bn  = (t & 15) * 4;    // 0..60

    const float* Aptr = A + (m_blk + am) * F + ak0;
    const float* Bptr = B + bk * FOURU + n_blk + bn;

    // prologue: stage 0
    float4 av = *(const float4*)Aptr;
    float4 bv = *(const float4*)Bptr;
    As2[0][ak0 + 0][am] = dup2(av.x);
    As2[0][ak0 + 1][am] = dup2(av.y);
    As2[0][ak0 + 2][am] = dup2(av.z);
    As2[0][ak0 + 3][am] = dup2(av.w);
    *(float4*)&Bs[0][bk][bn] = bv;
    __syncthreads();

    int buf = 0;
    for (int it = 0; it < NIT; ++it) {
        if (it + 1 < NIT) {               // prefetch next K-tile (global)
            Aptr += TK;
            Bptr += TK * FOURU;
            av = *(const float4*)Aptr;
            bv = *(const float4*)Bptr;
        }

#pragma unroll
        for (int kk = 0; kk < TK; ++kk) {
            ulonglong2 a01 = *(const ulonglong2*)&As2[buf][kk][tm];
            ulonglong2 a23 = *(const ulonglong2*)&As2[buf][kk][tm + 2];
            ulonglong2 b01 = *(const ulonglong2*)&Bs[buf][kk][tn];
            fma2(acc[0][0], a01.x, b01.x); fma2(acc[0][1], a01.x, b01.y);
            fma2(acc[1][0], a01.y, b01.x); fma2(acc[1][1], a01.y, b01.y);
            fma2(acc[2][0], a23.x, b01.x); fma2(acc[2][1], a23.x, b01.y);
            fma2(acc[3][0], a23.y, b01.x); fma2(acc[3][1], a23.y, b01.y);
        }

        if (it + 1 < NIT) {               // stage into the other buffer
            const int nb = buf ^ 1;
            As2[nb][ak0 + 0][am] = dup2(av.x);
            As2[nb][ak0 + 1][am] = dup2(av.y);
            As2[nb][ak0 + 2][am] = dup2(av.z);
            As2[nb][ak0 + 3][am] = dup2(av.w);
            *(float4*)&Bs[nb][bk][bn] = bv;
        }
        __syncthreads();
        buf ^= 1;
    }

#pragma unroll
    for (int mi = 0; mi < 4; ++mi) {
        float* zr = Zout + (m_blk + tm + mi) * FOURU + n_blk + tn;
        *(unsigned long long*)(zr)     = acc[mi][0];
        *(unsigned long long*)(zr + 2) = acc[mi][1];
    }
}

// ---------------- K4: gates + LSTM cell + scatter-max ----------------
__global__ void k_gates_scatter(const float* __restrict__ bias,
                                float* __restrict__ out_h,
                                float* __restrict__ out_newh,
                                float* __restrict__ out_newc) {
    const int i = blockIdx.x * blockDim.x + threadIdx.x;  // 0 .. BS*U-1
    const int b = i >> 9;     // / U
    const int u = i & (U - 1);

    const float* za = g_zpart[0] + b * FOURU;
    const float* zb = g_zpart[1] + b * FOURU;

    float zi = za[u]         + zb[u]         + bias[u];
    float zf = za[u + U]     + zb[u + U]     + bias[u + U];
    float zg = za[u + 2 * U] + zb[u + 2 * U] + bias[u + 2 * U];
    float zo = za[u + 3 * U] + zb[u + 3 * U] + bias[u + 3 * U];

    float ig = fsig(zi);
    float fg = fsig(zf);
    float gg = ftanh_fast(zg);
    float og = fsig(zo);

    float c0 = g_c0[i];
    float c  = fg * c0 + ig * gg;
    float h  = og * ftanh_fast(c);

    out_h[i] = h;

    const int cls = g_idx[b];
    atomicMaxFloat(&out_newh[cls * U + u], h);
    atomicMaxFloat(&out_newc[cls * U + u], c);
}

// ---------------- launch ----------------
extern "C" void kernel_launch(void* const* d_in, const int* in_sizes, int n_in,
                              void* d_out, int out_size) {
    const float* x        = (const float*)d_in[0];
    const float* logits   = (const float*)d_in[1];
    const float* h_states = (const float*)d_in[2];
    const float* c_states = (const float*)d_in[3];
    const float* kernelW  = (const float*)d_in[4];
    const float* recW     = (const float*)d_in[5];
    const float* bias     = (const float*)d_in[6];

    float* out      = (float*)d_out;
    float* out_h    = out;                    // (128, 512)
    float* out_newh = out + BS * U;           // (1024, 512)
    float* out_newc = out + BS * U + NC * U;  // (1024, 512)

    k_argmax_gather<<<BS, 256>>>(logits, h_states, c_states);
    k_copy_states<<<(NC * U / 4 + 255) / 256, 256>>>(h_states, c_states, out_newh, out_newc);
    dim3 g(FOURU / TN, BS / TM, 2);           // (32, 2, 2) = 128 blocks
    k_gemm<<<g, 256>>>(x, kernelW, recW);
    k_gates_scatter<<<(BS * U) / 256, 256>>>(bias, out_h, out_newh, out_newc);
}